// round 10
// baseline (speedup 1.0000x reference)
#include <cuda_runtime.h>
#include <cuda_fp16.h>
#include <cstdint>

#define FDIM 64
#define TWOF 128
#define NMAX 100000
#define EMAX 2000000
#define BETA 0.5f
#define NEGSLOPE 0.01f

static __device__ __align__(16) __half g_Ph[(size_t)NMAX * TWOF];   // P in fp16
static __device__ __align__(16) __half g_hh[(size_t)NMAX * FDIM];   // h in fp16
static __device__ __align__(16) float g_Wt[FDIM * TWOF];
static __device__ __align__(16) float g_colsum[FDIM];
static __device__ unsigned g_mm[4];
// CSR scratch
static __device__ int g_cnt[NMAX];
static __device__ int g_rowptr[NMAX + 1];
static __device__ int g_cur[NMAX];
static __device__ int g_part[128];
static __device__ __align__(16) uint2 g_edge[EMAX];  // {dst, ew bits} grouped by src

#define MM_BLKS 128
#define HIST_BLKS 256
#define HPREP_BLKS 256
#define WPREP_BLKS 32
#define PREP_BLKS (MM_BLKS + HIST_BLKS + HPREP_BLKS + WPREP_BLKS)
#define RE_BLKS 512
#define WIN 2048   // smem edge window for k_agg

__device__ __forceinline__ unsigned encf(float f) {
    unsigned u = __float_as_uint(f);
    return (u & 0x80000000u) ? ~u : (u | 0x80000000u);
}
__device__ __forceinline__ float decf(unsigned u) {
    return (u & 0x80000000u) ? __uint_as_float(u & 0x7FFFFFFFu) : __uint_as_float(~u);
}
__device__ __forceinline__ void ffma2(unsigned long long& d, unsigned long long a,
                                      unsigned long long b) {
    asm("fma.rn.f32x2 %0, %1, %2, %3;" : "=l"(d) : "l"(a), "l"(b), "l"(d));
}
__device__ __forceinline__ unsigned long long dup2(float x) {
    unsigned long long d;
    unsigned u = __float_as_uint(x);
    asm("mov.b64 %0, {%1, %1};" : "=l"(d) : "r"(u));
    return d;
}
__device__ __forceinline__ void unpack2(unsigned long long v, float& lo, float& hi) {
    unsigned a, b;
    asm("mov.b64 {%0, %1}, %2;" : "=r"(a), "=r"(b) : "l"(v));
    lo = __uint_as_float(a);
    hi = __uint_as_float(b);
}
__device__ __forceinline__ float4 h4_to_f4(uint2 p) {
    float2 lo = __half22float2(*(__half2*)&p.x);
    float2 hi = __half22float2(*(__half2*)&p.y);
    return make_float4(lo.x, lo.y, hi.x, hi.y);
}
__device__ __forceinline__ float lrelu_ew(float s, float ew) {
    return (s >= 0.f ? s : NEGSLOPE * s) * ew;
}

// ---------- init ----------
__global__ void k_init(int N) {
    int i = blockIdx.x * 256 + threadIdx.x;
    int4* c4 = (int4*)g_cnt;
    if (i < (N >> 2)) c4[i] = make_int4(0, 0, 0, 0);
    if (i == (N >> 2)) {
        for (int j = N & ~3; j < N; j++) g_cnt[j] = 0;
    }
    if (i < FDIM) g_colsum[i] = 0.0f;
    if (i == 0) {
        g_mm[0] = 0xFFFFFFFFu; g_mm[1] = 0u;
        g_mm[2] = 0xFFFFFFFFu; g_mm[3] = 0u;
    }
}

// ---------- fused prep: minmax | hist | h->fp16 | weight transpose ----------
__global__ void __launch_bounds__(256) k_prep(const float* __restrict__ amount,
                                              const float* __restrict__ count,
                                              const int* __restrict__ adj,
                                              const float* __restrict__ h,
                                              const float* __restrict__ fc_w,
                                              int E, int N) {
    int b = blockIdx.x;
    int tid = threadIdx.x;

    if (b < MM_BLKS) {
        int stride = MM_BLKS * 256;
        float amin = INFINITY, amax = -INFINITY, cmin = INFINITY, cmax = -INFINITY;
        int E4 = E >> 2;
        const float4* a4 = (const float4*)amount;
        const float4* c4 = (const float4*)count;
        for (int i = b * 256 + tid; i < E4; i += stride) {
            float4 a = a4[i], c = c4[i];
            amin = fminf(amin, fminf(fminf(a.x, a.y), fminf(a.z, a.w)));
            amax = fmaxf(amax, fmaxf(fmaxf(a.x, a.y), fmaxf(a.z, a.w)));
            cmin = fminf(cmin, fminf(fminf(c.x, c.y), fminf(c.z, c.w)));
            cmax = fmaxf(cmax, fmaxf(fmaxf(c.x, c.y), fmaxf(c.z, c.w)));
        }
        if (b == 0) {
            for (int i = (E4 << 2) + tid; i < E; i += 256) {
                float a = amount[i], c = count[i];
                amin = fminf(amin, a); amax = fmaxf(amax, a);
                cmin = fminf(cmin, c); cmax = fmaxf(cmax, c);
            }
        }
        #pragma unroll
        for (int off = 16; off; off >>= 1) {
            amin = fminf(amin, __shfl_down_sync(0xFFFFFFFFu, amin, off));
            amax = fmaxf(amax, __shfl_down_sync(0xFFFFFFFFu, amax, off));
            cmin = fminf(cmin, __shfl_down_sync(0xFFFFFFFFu, cmin, off));
            cmax = fmaxf(cmax, __shfl_down_sync(0xFFFFFFFFu, cmax, off));
        }
        __shared__ float red[4][8];
        int w = tid >> 5, l = tid & 31;
        if (l == 0) {
            red[0][w] = amin; red[1][w] = amax;
            red[2][w] = cmin; red[3][w] = cmax;
        }
        __syncthreads();
        if (tid == 0) {
            #pragma unroll
            for (int i = 1; i < 8; i++) {
                red[0][0] = fminf(red[0][0], red[0][i]);
                red[1][0] = fmaxf(red[1][0], red[1][i]);
                red[2][0] = fminf(red[2][0], red[2][i]);
                red[3][0] = fmaxf(red[3][0], red[3][i]);
            }
            atomicMin(&g_mm[0], encf(red[0][0]));
            atomicMax(&g_mm[1], encf(red[1][0]));
            atomicMin(&g_mm[2], encf(red[2][0]));
            atomicMax(&g_mm[3], encf(red[3][0]));
        }
    } else if (b < MM_BLKS + HIST_BLKS) {
        int rb = b - MM_BLKS;
        int stride = HIST_BLKS * 256;
        int E4 = E >> 2;
        const int4* a4 = (const int4*)adj;
        for (int i = rb * 256 + tid; i < E4; i += stride) {
            int4 s = a4[i];
            atomicAdd(&g_cnt[s.x], 1);
            atomicAdd(&g_cnt[s.y], 1);
            atomicAdd(&g_cnt[s.z], 1);
            atomicAdd(&g_cnt[s.w], 1);
        }
        if (rb == 0 && tid < (E & 3)) atomicAdd(&g_cnt[adj[(E & ~3) + tid]], 1);
    } else if (b < MM_BLKS + HIST_BLKS + HPREP_BLKS) {
        int rb = b - MM_BLKS - HIST_BLKS;
        int stride = HPREP_BLKS * 256;
        int total4 = (N * FDIM) >> 2;
        for (int i = rb * 256 + tid; i < total4; i += stride) {
            float4 v = ((const float4*)h)[i];
            __half2 a = __floats2half2_rn(v.x, v.y);
            __half2 bb = __floats2half2_rn(v.z, v.w);
            uint2 pk;
            pk.x = *(unsigned*)&a;
            pk.y = *(unsigned*)&bb;
            ((uint2*)g_hh)[i] = pk;
        }
    } else {
        int idx = (b - MM_BLKS - HIST_BLKS - HPREP_BLKS) * 256 + tid;
        if (idx < FDIM * TWOF) {
            int k = idx >> 7, c = idx & 127;
            g_Wt[idx] = (c < FDIM) ? fc_w[c * TWOF + k]
                                   : fc_w[(c - FDIM) * TWOF + FDIM + k];
        }
    }
}

// ---------- scans ----------
__global__ void __launch_bounds__(256) k_scanA(int N) {
    int base = blockIdx.x * 1024;
    int t = threadIdx.x;
    int s = 0;
    #pragma unroll
    for (int i = t; i < 1024; i += 256) {
        int idx = base + i;
        s += (idx < N) ? g_cnt[idx] : 0;
    }
    __shared__ int red[256];
    red[t] = s;
    __syncthreads();
    #pragma unroll
    for (int off = 128; off; off >>= 1) {
        if (t < off) red[t] += red[t + off];
        __syncthreads();
    }
    if (t == 0) g_part[blockIdx.x] = red[0];
}

// parallel exclusive scan of <=128 partials
__global__ void __launch_bounds__(128) k_scanB(int nchunks, int E, int N) {
    int t = threadIdx.x;
    int v = (t < nchunks) ? g_part[t] : 0;
    __shared__ int sp[128];
    sp[t] = v;
    __syncthreads();
    #pragma unroll
    for (int off = 1; off < 128; off <<= 1) {
        int x = (t >= off) ? sp[t - off] : 0;
        __syncthreads();
        sp[t] += x;
        __syncthreads();
    }
    if (t < nchunks) g_part[t] = sp[t] - v;  // exclusive
    if (t == 0) g_rowptr[N] = E;
}

__global__ void __launch_bounds__(256) k_scanC(int N) {
    int b = blockIdx.x, t = threadIdx.x;
    int base = b * 1024 + t * 4;
    int v[4];
    #pragma unroll
    for (int j = 0; j < 4; j++) v[j] = (base + j < N) ? g_cnt[base + j] : 0;
    int local = v[0] + v[1] + v[2] + v[3];
    __shared__ int sums[256];
    sums[t] = local;
    __syncthreads();
    #pragma unroll
    for (int off = 1; off < 256; off <<= 1) {
        int x = (t >= off) ? sums[t - off] : 0;
        __syncthreads();
        sums[t] += x;
        __syncthreads();
    }
    int excl = sums[t] - local + g_part[b];
    #pragma unroll
    for (int j = 0; j < 4; j++) {
        if (base + j < N) {
            g_rowptr[base + j] = excl;
            g_cur[base + j] = excl;
        }
        excl += v[j];
    }
}

// ---------- fused main: GEMM | edge reorder ----------
#define GN 64
__global__ void __launch_bounds__(256) k_main(const float* __restrict__ h,
                                              const float* __restrict__ fc_b,
                                              const int* __restrict__ adj,
                                              const float* __restrict__ amount,
                                              const float* __restrict__ count,
                                              int E, int N, int gemmBlocks) {
    __shared__ __align__(16) float hs[GN][68];
    int tid = threadIdx.x;

    if ((int)blockIdx.x < gemmBlocks) {
        int n0 = blockIdx.x * GN;
        {
            const float4* h4 = (const float4*)h;
            for (int idx = tid; idx < GN * (FDIM / 4); idx += 256) {
                int n = idx >> 4, kq = idx & 15;
                int gn = n0 + n;
                float4 v = (gn < N) ? h4[(size_t)gn * (FDIM / 4) + kq]
                                    : make_float4(0.f, 0.f, 0.f, 0.f);
                *(float4*)&hs[n][kq * 4] = v;
            }
        }
        __syncthreads();

        int tx = tid & 15, ty = tid >> 4;
        int c0 = tx * 8;
        int nb = ty * 4;

        unsigned long long acc[4][4];
        #pragma unroll
        for (int i = 0; i < 4; i++)
            #pragma unroll
            for (int j = 0; j < 4; j++) acc[i][j] = 0ull;

        #pragma unroll 4
        for (int k = 0; k < FDIM; k++) {
            const ulonglong2* bp = (const ulonglong2*)(g_Wt + k * TWOF + c0);
            ulonglong2 b01 = __ldg(bp);
            ulonglong2 b23 = __ldg(bp + 1);
            #pragma unroll
            for (int i = 0; i < 4; i++) {
                unsigned long long a2 = dup2(hs[nb + i][k]);
                ffma2(acc[i][0], a2, b01.x);
                ffma2(acc[i][1], a2, b01.y);
                ffma2(acc[i][2], a2, b23.x);
                ffma2(acc[i][3], a2, b23.y);
            }
        }

        float bias[8];
        #pragma unroll
        for (int j = 0; j < 8; j++)
            bias[j] = (c0 >= FDIM) ? __ldg(&fc_b[c0 + j - FDIM]) : 0.0f;

        #pragma unroll
        for (int i = 0; i < 4; i++) {
            int gn = n0 + nb + i;
            if (gn >= N) continue;
            float o[8];
            #pragma unroll
            for (int j = 0; j < 4; j++) unpack2(acc[i][j], o[2 * j], o[2 * j + 1]);
            __half2 ha = __floats2half2_rn(o[0] + bias[0], o[1] + bias[1]);
            __half2 hb = __floats2half2_rn(o[2] + bias[2], o[3] + bias[3]);
            __half2 hc = __floats2half2_rn(o[4] + bias[4], o[5] + bias[5]);
            __half2 hd = __floats2half2_rn(o[6] + bias[6], o[7] + bias[7]);
            uint4 pk;
            pk.x = *(unsigned*)&ha; pk.y = *(unsigned*)&hb;
            pk.z = *(unsigned*)&hc; pk.w = *(unsigned*)&hd;
            *(uint4*)(g_Ph + (size_t)gn * TWOF + c0) = pk;
        }
    } else {
        int rb = blockIdx.x - gemmBlocks;
        float amin = decf(g_mm[0]), amax = decf(g_mm[1]);
        float cmin = decf(g_mm[2]), cmax = decf(g_mm[3]);
        float as = BETA / (amax - amin + 1e-8f);
        float cs = (1.0f - BETA) / (cmax - cmin + 1e-8f);
        int stride = RE_BLKS * 256;
        for (int e = rb * 256 + tid; e < E; e += stride) {
            int s = adj[e];
            int d = adj[E + e];
            float ew = (amount[e] - amin) * as + (count[e] - cmin) * cs;
            int pos = atomicAdd(&g_cur[s], 1);
            g_edge[pos] = make_uint2((unsigned)d, __float_as_uint(ew));
        }
    }
}

// ---------- aggregate: 16 contiguous rows/block, smem-staged edge windows ----------
__global__ void __launch_bounds__(256) k_agg(float* __restrict__ out, int N) {
    __shared__ __align__(16) uint2 sedge[WIN];
    __shared__ int srow[17];
    int tid = threadIdx.x;
    int lane16 = tid & 15;
    int egrp = tid >> 4;
    int co = lane16 * 4;
    int row0 = blockIdx.x * 16;

    if (tid < 17) {
        int r = row0 + tid;
        srow[tid] = g_rowptr[r < N ? r : N];
    }
    __syncthreads();
    int blockStart = srow[0];
    int blockEnd = srow[16];
    int myRow = row0 + egrp;
    bool active = myRow < N;
    int e0 = active ? srow[egrp] : 0;
    int e1 = active ? srow[egrp + 1] : 0;

    float4 p1 = make_float4(0.f, 0.f, 0.f, 0.f);
    if (active) p1 = h4_to_f4(*(const uint2*)(g_Ph + (size_t)myRow * TWOF + co));
    float4 o = make_float4(0.f, 0.f, 0.f, 0.f);
    float4 cacc = make_float4(0.f, 0.f, 0.f, 0.f);

    for (int wb = blockStart; wb < blockEnd; wb += WIN) {
        int we = wb + WIN < blockEnd ? wb + WIN : blockEnd;
        int cnt = we - wb;
        __syncthreads();  // previous window consumed
        for (int i = tid; i < cnt; i += 256) sedge[i] = g_edge[wb + i];
        __syncthreads();

        int s = e0 > wb ? e0 : wb;
        int t = e1 < we ? e1 : we;
        int e = s;
        for (; e + 2 <= t; e += 2) {
            uint2 ed0 = sedge[e - wb];
            uint2 ed1 = sedge[e - wb + 1];
            int d0 = (int)ed0.x, d1 = (int)ed1.x;
            uint2 q2a = __ldg((const uint2*)(g_Ph + (size_t)d0 * TWOF + FDIM + co));
            uint2 qha = __ldg((const uint2*)(g_hh + (size_t)d0 * FDIM + co));
            uint2 q2b = __ldg((const uint2*)(g_Ph + (size_t)d1 * TWOF + FDIM + co));
            uint2 qhb = __ldg((const uint2*)(g_hh + (size_t)d1 * FDIM + co));
            float ew0 = __uint_as_float(ed0.y);
            float ew1 = __uint_as_float(ed1.y);
            {
                float4 p2 = h4_to_f4(q2a), hv = h4_to_f4(qha);
                float ex = __expf(lrelu_ew(p1.x + p2.x, ew0));
                float ey = __expf(lrelu_ew(p1.y + p2.y, ew0));
                float ez = __expf(lrelu_ew(p1.z + p2.z, ew0));
                float ew_ = __expf(lrelu_ew(p1.w + p2.w, ew0));
                cacc.x += ex; cacc.y += ey; cacc.z += ez; cacc.w += ew_;
                o.x += ex * hv.x; o.y += ey * hv.y; o.z += ez * hv.z; o.w += ew_ * hv.w;
            }
            {
                float4 p2 = h4_to_f4(q2b), hv = h4_to_f4(qhb);
                float ex = __expf(lrelu_ew(p1.x + p2.x, ew1));
                float ey = __expf(lrelu_ew(p1.y + p2.y, ew1));
                float ez = __expf(lrelu_ew(p1.z + p2.z, ew1));
                float ew_ = __expf(lrelu_ew(p1.w + p2.w, ew1));
                cacc.x += ex; cacc.y += ey; cacc.z += ez; cacc.w += ew_;
                o.x += ex * hv.x; o.y += ey * hv.y; o.z += ez * hv.z; o.w += ew_ * hv.w;
            }
        }
        if (e < t) {
            uint2 ed0 = sedge[e - wb];
            int d0 = (int)ed0.x;
            float ew0 = __uint_as_float(ed0.y);
            float4 p2 = h4_to_f4(__ldg((const uint2*)(g_Ph + (size_t)d0 * TWOF + FDIM + co)));
            float4 hv = h4_to_f4(__ldg((const uint2*)(g_hh + (size_t)d0 * FDIM + co)));
            float ex = __expf(lrelu_ew(p1.x + p2.x, ew0));
            float ey = __expf(lrelu_ew(p1.y + p2.y, ew0));
            float ez = __expf(lrelu_ew(p1.z + p2.z, ew0));
            float ew_ = __expf(lrelu_ew(p1.w + p2.w, ew0));
            cacc.x += ex; cacc.y += ey; cacc.z += ez; cacc.w += ew_;
            o.x += ex * hv.x; o.y += ey * hv.y; o.z += ez * hv.z; o.w += ew_ * hv.w;
        }
    }

    if (active) *(float4*)(out + (size_t)myRow * FDIM + co) = o;

    __shared__ float scol[FDIM];
    __syncthreads();
    if (tid < FDIM) scol[tid] = 0.0f;
    __syncthreads();
    atomicAdd(&scol[co + 0], cacc.x);
    atomicAdd(&scol[co + 1], cacc.y);
    atomicAdd(&scol[co + 2], cacc.z);
    atomicAdd(&scol[co + 3], cacc.w);
    __syncthreads();
    if (tid < FDIM) atomicAdd(&g_colsum[tid], scol[tid]);
}

// ---------- normalize ----------
__global__ void __launch_bounds__(256) k_norm(float* __restrict__ out, int total4) {
    int i = blockIdx.x * blockDim.x + threadIdx.x;
    if (i >= total4) return;
    float4 cs4 = *(const float4*)(g_colsum + (i & 15) * 4);
    float4 v = ((float4*)out)[i];
    v.x = v.x / cs4.x;
    v.y = v.y / cs4.y;
    v.z = v.z / cs4.z;
    v.w = v.w / cs4.w;
    ((float4*)out)[i] = v;
}

extern "C" void kernel_launch(void* const* d_in, const int* in_sizes, int n_in,
                              void* d_out, int out_size) {
    const float* h = (const float*)d_in[0];
    const int* adj = (const int*)d_in[1];
    const float* amount = (const float*)d_in[2];
    const float* count = (const float*)d_in[3];
    const float* fc_w = (const float*)d_in[4];
    const float* fc_b = (const float*)d_in[5];
    float* out = (float*)d_out;

    int N = in_sizes[0] / FDIM;
    int E = in_sizes[2];
    int nchunks = (N + 1023) / 1024;
    int gemmBlocks = (N + GN - 1) / GN;

    k_init<<<(N / 4 + 256) / 256, 256>>>(N);
    k_prep<<<PREP_BLKS, 256>>>(amount, count, adj, h, fc_w, E, N);
    k_scanA<<<nchunks, 256>>>(N);
    k_scanB<<<1, 128>>>(nchunks, E, N);
    k_scanC<<<nchunks, 256>>>(N);
    k_main<<<gemmBlocks + RE_BLKS, 256>>>(h, fc_b, adj, amount, count, E, N, gemmBlocks);
    k_agg<<<(N + 15) / 16, 256>>>(out, N);
    int total4 = out_size / 4;
    k_norm<<<(total4 + 255) / 256, 256>>>(out, total4);
}

// round 13
// speedup vs baseline: 1.0529x; 1.0529x over previous
#include <cuda_runtime.h>
#include <cuda_fp16.h>
#include <cstdint>

#define FDIM 64
#define TWOF 128
#define NMAX 100000
#define EMAX 2000000
#define BETA 0.5f
#define NEGSLOPE 0.01f

static __device__ __align__(16) __half g_Ph[(size_t)NMAX * TWOF];   // P in fp16
static __device__ __align__(16) __half g_hh[(size_t)NMAX * FDIM];   // h in fp16
static __device__ __align__(16) float g_Wt[FDIM * TWOF];
static __device__ __align__(16) float g_colsum[FDIM];
static __device__ unsigned g_mm[4];
static __device__ int g_cnt[NMAX];
static __device__ int g_rowptr[NMAX + 1];
static __device__ int g_cur[NMAX];
static __device__ int g_part[128];
static __device__ __align__(16) uint2 g_edge[EMAX];  // {dst, ew bits} grouped by src

#define MM_BLKS 128
#define HIST_BLKS 256
#define HPREP_BLKS 256
#define WPREP_BLKS 32
#define PREP_BLKS (MM_BLKS + HIST_BLKS + HPREP_BLKS + WPREP_BLKS)
#define RE_BLKS 512

__device__ __forceinline__ unsigned encf(float f) {
    unsigned u = __float_as_uint(f);
    return (u & 0x80000000u) ? ~u : (u | 0x80000000u);
}
__device__ __forceinline__ float decf(unsigned u) {
    return (u & 0x80000000u) ? __uint_as_float(u & 0x7FFFFFFFu) : __uint_as_float(~u);
}
__device__ __forceinline__ void ffma2(unsigned long long& d, unsigned long long a,
                                      unsigned long long b) {
    asm("fma.rn.f32x2 %0, %1, %2, %3;" : "=l"(d) : "l"(a), "l"(b), "l"(d));
}
__device__ __forceinline__ unsigned long long dup2(float x) {
    unsigned long long d;
    unsigned u = __float_as_uint(x);
    asm("mov.b64 %0, {%1, %1};" : "=l"(d) : "r"(u));
    return d;
}
__device__ __forceinline__ void unpack2(unsigned long long v, float& lo, float& hi) {
    unsigned a, b;
    asm("mov.b64 {%0, %1}, %2;" : "=r"(a), "=r"(b) : "l"(v));
    lo = __uint_as_float(a);
    hi = __uint_as_float(b);
}
__device__ __forceinline__ float4 h4_to_f4(uint2 p) {
    float2 lo = __half22float2(*(__half2*)&p.x);
    float2 hi = __half22float2(*(__half2*)&p.y);
    return make_float4(lo.x, lo.y, hi.x, hi.y);
}
// sum two half2-pairs in fp16, convert the SUM once to fp32
__device__ __forceinline__ float4 score_f4(uint2 p1, uint2 p2) {
    __half2 s0 = __hadd2(*(__half2*)&p1.x, *(__half2*)&p2.x);
    __half2 s1 = __hadd2(*(__half2*)&p1.y, *(__half2*)&p2.y);
    float2 lo = __half22float2(s0);
    float2 hi = __half22float2(s1);
    return make_float4(lo.x, lo.y, hi.x, hi.y);
}
__device__ __forceinline__ float lrelu_ew(float s, float ew) {
    return (s >= 0.f ? s : NEGSLOPE * s) * ew;
}

// ---------- init ----------
__global__ void k_init(int N) {
    int i = blockIdx.x * 256 + threadIdx.x;
    int4* c4 = (int4*)g_cnt;
    if (i < (N >> 2)) c4[i] = make_int4(0, 0, 0, 0);
    if (i == (N >> 2)) {
        for (int j = N & ~3; j < N; j++) g_cnt[j] = 0;
    }
    if (i < FDIM) g_colsum[i] = 0.0f;
    if (i == 0) {
        g_mm[0] = 0xFFFFFFFFu; g_mm[1] = 0u;
        g_mm[2] = 0xFFFFFFFFu; g_mm[3] = 0u;
    }
}

// ---------- fused prep: minmax | hist | h->fp16 | weight transpose ----------
__global__ void __launch_bounds__(256) k_prep(const float* __restrict__ amount,
                                              const float* __restrict__ count,
                                              const int* __restrict__ adj,
                                              const float* __restrict__ h,
                                              const float* __restrict__ fc_w,
                                              int E, int N) {
    int b = blockIdx.x;
    int tid = threadIdx.x;

    if (b < MM_BLKS) {
        int stride = MM_BLKS * 256;
        float amin = INFINITY, amax = -INFINITY, cmin = INFINITY, cmax = -INFINITY;
        int E4 = E >> 2;
        const float4* a4 = (const float4*)amount;
        const float4* c4 = (const float4*)count;
        for (int i = b * 256 + tid; i < E4; i += stride) {
            float4 a = a4[i], c = c4[i];
            amin = fminf(amin, fminf(fminf(a.x, a.y), fminf(a.z, a.w)));
            amax = fmaxf(amax, fmaxf(fmaxf(a.x, a.y), fmaxf(a.z, a.w)));
            cmin = fminf(cmin, fminf(fminf(c.x, c.y), fminf(c.z, c.w)));
            cmax = fmaxf(cmax, fmaxf(fmaxf(c.x, c.y), fmaxf(c.z, c.w)));
        }
        if (b == 0) {
            for (int i = (E4 << 2) + tid; i < E; i += 256) {
                float a = amount[i], c = count[i];
                amin = fminf(amin, a); amax = fmaxf(amax, a);
                cmin = fminf(cmin, c); cmax = fmaxf(cmax, c);
            }
        }
        #pragma unroll
        for (int off = 16; off; off >>= 1) {
            amin = fminf(amin, __shfl_down_sync(0xFFFFFFFFu, amin, off));
            amax = fmaxf(amax, __shfl_down_sync(0xFFFFFFFFu, amax, off));
            cmin = fminf(cmin, __shfl_down_sync(0xFFFFFFFFu, cmin, off));
            cmax = fmaxf(cmax, __shfl_down_sync(0xFFFFFFFFu, cmax, off));
        }
        __shared__ float red[4][8];
        int w = tid >> 5, l = tid & 31;
        if (l == 0) {
            red[0][w] = amin; red[1][w] = amax;
            red[2][w] = cmin; red[3][w] = cmax;
        }
        __syncthreads();
        if (tid == 0) {
            #pragma unroll
            for (int i = 1; i < 8; i++) {
                red[0][0] = fminf(red[0][0], red[0][i]);
                red[1][0] = fmaxf(red[1][0], red[1][i]);
                red[2][0] = fminf(red[2][0], red[2][i]);
                red[3][0] = fmaxf(red[3][0], red[3][i]);
            }
            atomicMin(&g_mm[0], encf(red[0][0]));
            atomicMax(&g_mm[1], encf(red[1][0]));
            atomicMin(&g_mm[2], encf(red[2][0]));
            atomicMax(&g_mm[3], encf(red[3][0]));
        }
    } else if (b < MM_BLKS + HIST_BLKS) {
        int rb = b - MM_BLKS;
        int stride = HIST_BLKS * 256;
        int E4 = E >> 2;
        const int4* a4 = (const int4*)adj;
        for (int i = rb * 256 + tid; i < E4; i += stride) {
            int4 s = a4[i];
            atomicAdd(&g_cnt[s.x], 1);
            atomicAdd(&g_cnt[s.y], 1);
            atomicAdd(&g_cnt[s.z], 1);
            atomicAdd(&g_cnt[s.w], 1);
        }
        if (rb == 0 && tid < (E & 3)) atomicAdd(&g_cnt[adj[(E & ~3) + tid]], 1);
    } else if (b < MM_BLKS + HIST_BLKS + HPREP_BLKS) {
        int rb = b - MM_BLKS - HIST_BLKS;
        int stride = HPREP_BLKS * 256;
        int total4 = (N * FDIM) >> 2;
        for (int i = rb * 256 + tid; i < total4; i += stride) {
            float4 v = ((const float4*)h)[i];
            __half2 a = __floats2half2_rn(v.x, v.y);
            __half2 bb = __floats2half2_rn(v.z, v.w);
            uint2 pk;
            pk.x = *(unsigned*)&a;
            pk.y = *(unsigned*)&bb;
            ((uint2*)g_hh)[i] = pk;
        }
    } else {
        int idx = (b - MM_BLKS - HIST_BLKS - HPREP_BLKS) * 256 + tid;
        if (idx < FDIM * TWOF) {
            int k = idx >> 7, c = idx & 127;
            g_Wt[idx] = (c < FDIM) ? fc_w[c * TWOF + k]
                                   : fc_w[(c - FDIM) * TWOF + FDIM + k];
        }
    }
}

// ---------- scans ----------
__global__ void __launch_bounds__(256) k_scanA(int N) {
    int base = blockIdx.x * 1024;
    int t = threadIdx.x;
    int s = 0;
    #pragma unroll
    for (int i = t; i < 1024; i += 256) {
        int idx = base + i;
        s += (idx < N) ? g_cnt[idx] : 0;
    }
    __shared__ int red[256];
    red[t] = s;
    __syncthreads();
    #pragma unroll
    for (int off = 128; off; off >>= 1) {
        if (t < off) red[t] += red[t + off];
        __syncthreads();
    }
    if (t == 0) g_part[blockIdx.x] = red[0];
}

__global__ void __launch_bounds__(128) k_scanB(int nchunks, int E, int N) {
    int t = threadIdx.x;
    int v = (t < nchunks) ? g_part[t] : 0;
    __shared__ int sp[128];
    sp[t] = v;
    __syncthreads();
    #pragma unroll
    for (int off = 1; off < 128; off <<= 1) {
        int x = (t >= off) ? sp[t - off] : 0;
        __syncthreads();
        sp[t] += x;
        __syncthreads();
    }
    if (t < nchunks) g_part[t] = sp[t] - v;
    if (t == 0) g_rowptr[N] = E;
}

__global__ void __launch_bounds__(256) k_scanC(int N) {
    int b = blockIdx.x, t = threadIdx.x;
    int base = b * 1024 + t * 4;
    int v[4];
    #pragma unroll
    for (int j = 0; j < 4; j++) v[j] = (base + j < N) ? g_cnt[base + j] : 0;
    int local = v[0] + v[1] + v[2] + v[3];
    __shared__ int sums[256];
    sums[t] = local;
    __syncthreads();
    #pragma unroll
    for (int off = 1; off < 256; off <<= 1) {
        int x = (t >= off) ? sums[t - off] : 0;
        __syncthreads();
        sums[t] += x;
        __syncthreads();
    }
    int excl = sums[t] - local + g_part[b];
    #pragma unroll
    for (int j = 0; j < 4; j++) {
        if (base + j < N) {
            g_rowptr[base + j] = excl;
            g_cur[base + j] = excl;
        }
        excl += v[j];
    }
}

// ---------- fused main: GEMM | edge reorder ----------
#define GN 64
__global__ void __launch_bounds__(256) k_main(const float* __restrict__ h,
                                              const float* __restrict__ fc_b,
                                              const int* __restrict__ adj,
                                              const float* __restrict__ amount,
                                              const float* __restrict__ count,
                                              int E, int N, int gemmBlocks) {
    __shared__ __align__(16) float hs[GN][68];
    int tid = threadIdx.x;

    if ((int)blockIdx.x < gemmBlocks) {
        int n0 = blockIdx.x * GN;
        {
            const float4* h4 = (const float4*)h;
            for (int idx = tid; idx < GN * (FDIM / 4); idx += 256) {
                int n = idx >> 4, kq = idx & 15;
                int gn = n0 + n;
                float4 v = (gn < N) ? h4[(size_t)gn * (FDIM / 4) + kq]
                                    : make_float4(0.f, 0.f, 0.f, 0.f);
                *(float4*)&hs[n][kq * 4] = v;
            }
        }
        __syncthreads();

        int tx = tid & 15, ty = tid >> 4;
        int c0 = tx * 8;
        int nb = ty * 4;

        unsigned long long acc[4][4];
        #pragma unroll
        for (int i = 0; i < 4; i++)
            #pragma unroll
            for (int j = 0; j < 4; j++) acc[i][j] = 0ull;

        #pragma unroll 4
        for (int k = 0; k < FDIM; k++) {
            const ulonglong2* bp = (const ulonglong2*)(g_Wt + k * TWOF + c0);
            ulonglong2 b01 = __ldg(bp);
            ulonglong2 b23 = __ldg(bp + 1);
            #pragma unroll
            for (int i = 0; i < 4; i++) {
                unsigned long long a2 = dup2(hs[nb + i][k]);
                ffma2(acc[i][0], a2, b01.x);
                ffma2(acc[i][1], a2, b01.y);
                ffma2(acc[i][2], a2, b23.x);
                ffma2(acc[i][3], a2, b23.y);
            }
        }

        float bias[8];
        #pragma unroll
        for (int j = 0; j < 8; j++)
            bias[j] = (c0 >= FDIM) ? __ldg(&fc_b[c0 + j - FDIM]) : 0.0f;

        #pragma unroll
        for (int i = 0; i < 4; i++) {
            int gn = n0 + nb + i;
            if (gn >= N) continue;
            float o[8];
            #pragma unroll
            for (int j = 0; j < 4; j++) unpack2(acc[i][j], o[2 * j], o[2 * j + 1]);
            __half2 ha = __floats2half2_rn(o[0] + bias[0], o[1] + bias[1]);
            __half2 hb = __floats2half2_rn(o[2] + bias[2], o[3] + bias[3]);
            __half2 hc = __floats2half2_rn(o[4] + bias[4], o[5] + bias[5]);
            __half2 hd = __floats2half2_rn(o[6] + bias[6], o[7] + bias[7]);
            uint4 pk;
            pk.x = *(unsigned*)&ha; pk.y = *(unsigned*)&hb;
            pk.z = *(unsigned*)&hc; pk.w = *(unsigned*)&hd;
            *(uint4*)(g_Ph + (size_t)gn * TWOF + c0) = pk;
        }
    } else {
        int rb = blockIdx.x - gemmBlocks;
        float amin = decf(g_mm[0]), amax = decf(g_mm[1]);
        float cmin = decf(g_mm[2]), cmax = decf(g_mm[3]);
        float as = BETA / (amax - amin + 1e-8f);
        float cs = (1.0f - BETA) / (cmax - cmin + 1e-8f);
        int stride = RE_BLKS * 256;
        for (int e = rb * 256 + tid; e < E; e += stride) {
            int s = adj[e];
            int d = adj[E + e];
            float ew = (amount[e] - amin) * as + (count[e] - cmin) * cs;
            int pos = atomicAdd(&g_cur[s], 1);
            g_edge[pos] = make_uint2((unsigned)d, __float_as_uint(ew));
        }
    }
}

// ---------- aggregate: one node per 16-lane group, 4-edge unroll, half2 score add ----------
__global__ void __launch_bounds__(256) k_agg(float* __restrict__ out, int N) {
    int lane16 = threadIdx.x & 15;
    int egrp = threadIdx.x >> 4;
    int co = lane16 * 4;

    float4 cacc = make_float4(0.f, 0.f, 0.f, 0.f);

    for (int n = blockIdx.x * 16 + egrp; n < N; n += gridDim.x * 16) {
        int e = g_rowptr[n];
        int end = g_rowptr[n + 1];
        uint2 p1q = *(const uint2*)(g_Ph + (size_t)n * TWOF + co);
        float4 o = make_float4(0.f, 0.f, 0.f, 0.f);

        for (; e + 4 <= end; e += 4) {
            uint2 ed0 = __ldg(&g_edge[e]);
            uint2 ed1 = __ldg(&g_edge[e + 1]);
            uint2 ed2 = __ldg(&g_edge[e + 2]);
            uint2 ed3 = __ldg(&g_edge[e + 3]);
            uint2 q2a = *(const uint2*)(g_Ph + (size_t)(int)ed0.x * TWOF + FDIM + co);
            uint2 qha = *(const uint2*)(g_hh + (size_t)(int)ed0.x * FDIM + co);
            uint2 q2b = *(const uint2*)(g_Ph + (size_t)(int)ed1.x * TWOF + FDIM + co);
            uint2 qhb = *(const uint2*)(g_hh + (size_t)(int)ed1.x * FDIM + co);
            uint2 q2c = *(const uint2*)(g_Ph + (size_t)(int)ed2.x * TWOF + FDIM + co);
            uint2 qhc = *(const uint2*)(g_hh + (size_t)(int)ed2.x * FDIM + co);
            uint2 q2d = *(const uint2*)(g_Ph + (size_t)(int)ed3.x * TWOF + FDIM + co);
            uint2 qhd = *(const uint2*)(g_hh + (size_t)(int)ed3.x * FDIM + co);

            {
                float ew0 = __uint_as_float(ed0.y);
                float4 s = score_f4(p1q, q2a);
                float4 hv = h4_to_f4(qha);
                float ex = __expf(lrelu_ew(s.x, ew0));
                float ey = __expf(lrelu_ew(s.y, ew0));
                float ez = __expf(lrelu_ew(s.z, ew0));
                float ew_ = __expf(lrelu_ew(s.w, ew0));
                cacc.x += ex; cacc.y += ey; cacc.z += ez; cacc.w += ew_;
                o.x += ex * hv.x; o.y += ey * hv.y; o.z += ez * hv.z; o.w += ew_ * hv.w;
            }
            {
                float ew1 = __uint_as_float(ed1.y);
                float4 s = score_f4(p1q, q2b);
                float4 hv = h4_to_f4(qhb);
                float ex = __expf(lrelu_ew(s.x, ew1));
                float ey = __expf(lrelu_ew(s.y, ew1));
                float ez = __expf(lrelu_ew(s.z, ew1));
                float ew_ = __expf(lrelu_ew(s.w, ew1));
                cacc.x += ex; cacc.y += ey; cacc.z += ez; cacc.w += ew_;
                o.x += ex * hv.x; o.y += ey * hv.y; o.z += ez * hv.z; o.w += ew_ * hv.w;
            }
            {
                float ew2 = __uint_as_float(ed2.y);
                float4 s = score_f4(p1q, q2c);
                float4 hv = h4_to_f4(qhc);
                float ex = __expf(lrelu_ew(s.x, ew2));
                float ey = __expf(lrelu_ew(s.y, ew2));
                float ez = __expf(lrelu_ew(s.z, ew2));
                float ew_ = __expf(lrelu_ew(s.w, ew2));
                cacc.x += ex; cacc.y += ey; cacc.z += ez; cacc.w += ew_;
                o.x += ex * hv.x; o.y += ey * hv.y; o.z += ez * hv.z; o.w += ew_ * hv.w;
            }
            {
                float ew3 = __uint_as_float(ed3.y);
                float4 s = score_f4(p1q, q2d);
                float4 hv = h4_to_f4(qhd);
                float ex = __expf(lrelu_ew(s.x, ew3));
                float ey = __expf(lrelu_ew(s.y, ew3));
                float ez = __expf(lrelu_ew(s.z, ew3));
                float ew_ = __expf(lrelu_ew(s.w, ew3));
                cacc.x += ex; cacc.y += ey; cacc.z += ez; cacc.w += ew_;
                o.x += ex * hv.x; o.y += ey * hv.y; o.z += ez * hv.z; o.w += ew_ * hv.w;
            }
        }
        for (; e < end; e++) {
            uint2 ed0 = __ldg(&g_edge[e]);
            int d0 = (int)ed0.x;
            float ew0 = __uint_as_float(ed0.y);
            uint2 q2 = *(const uint2*)(g_Ph + (size_t)d0 * TWOF + FDIM + co);
            float4 s = score_f4(p1q, q2);
            float4 hv = h4_to_f4(*(const uint2*)(g_hh + (size_t)d0 * FDIM + co));
            float ex = __expf(lrelu_ew(s.x, ew0));
            float ey = __expf(lrelu_ew(s.y, ew0));
            float ez = __expf(lrelu_ew(s.z, ew0));
            float ew_ = __expf(lrelu_ew(s.w, ew0));
            cacc.x += ex; cacc.y += ey; cacc.z += ez; cacc.w += ew_;
            o.x += ex * hv.x; o.y += ey * hv.y; o.z += ez * hv.z; o.w += ew_ * hv.w;
        }
        *(float4*)(out + (size_t)n * FDIM + co) = o;
    }

    __shared__ float scol[FDIM];
    if (threadIdx.x < FDIM) scol[threadIdx.x] = 0.0f;
    __syncthreads();
    atomicAdd(&scol[co + 0], cacc.x);
    atomicAdd(&scol[co + 1], cacc.y);
    atomicAdd(&scol[co + 2], cacc.z);
    atomicAdd(&scol[co + 3], cacc.w);
    __syncthreads();
    if (threadIdx.x < FDIM) atomicAdd(&g_colsum[threadIdx.x], scol[threadIdx.x]);
}

// ---------- normalize (approx divide: FMUL+MUFU instead of full-precision div) ----------
__global__ void __launch_bounds__(256) k_norm(float* __restrict__ out, int total4) {
    int i = blockIdx.x * blockDim.x + threadIdx.x;
    if (i >= total4) return;
    float4 cs4 = *(const float4*)(g_colsum + (i & 15) * 4);
    float4 v = ((float4*)out)[i];
    v.x = __fdividef(v.x, cs4.x);
    v.y = __fdividef(v.y, cs4.y);
    v.z = __fdividef(v.z, cs4.z);
    v.w = __fdividef(v.w, cs4.w);
    ((float4*)out)[i] = v;
}

extern "C" void kernel_launch(void* const* d_in, const int* in_sizes, int n_in,
                              void* d_out, int out_size) {
    const float* h = (const float*)d_in[0];
    const int* adj = (const int*)d_in[1];
    const float* amount = (const float*)d_in[2];
    const float* count = (const float*)d_in[3];
    const float* fc_w = (const float*)d_in[4];
    const float* fc_b = (const float*)d_in[5];
    float* out = (float*)d_out;

    int N = in_sizes[0] / FDIM;
    int E = in_sizes[2];
    int nchunks = (N + 1023) / 1024;
    int gemmBlocks = (N + GN - 1) / GN;

    k_init<<<(N / 4 + 256) / 256, 256>>>(N);
    k_prep<<<PREP_BLKS, 256>>>(amount, count, adj, h, fc_w, E, N);
    k_scanA<<<nchunks, 256>>>(N);
    k_scanB<<<1, 128>>>(nchunks, E, N);
    k_scanC<<<nchunks, 256>>>(N);
    k_main<<<gemmBlocks + RE_BLKS, 256>>>(h, fc_b, adj, amount, count, E, N, gemmBlocks);
    k_agg<<<(N + 15) / 16, 256>>>(out, N);
    int total4 = out_size / 4;
    k_norm<<<(total4 + 255) / 256, 256>>>(out, total4);
}

// round 14
// speedup vs baseline: 1.0599x; 1.0067x over previous
#include <cuda_runtime.h>
#include <cuda_fp16.h>
#include <cstdint>

#define FDIM 64
#define TWOF 128
#define NMAX 100000
#define EMAX 2000000
#define BETA 0.5f
#define NEGSLOPE 0.01f

static __device__ __align__(16) __half g_P1[(size_t)NMAX * FDIM];   // P1 (cols 0..63), fp16
// interleaved per node: 16 groups of [P2(4 cols) | h(4 cols)] halves
static __device__ __align__(16) __half g_kv[(size_t)NMAX * TWOF];
static __device__ __align__(16) float g_Wt[FDIM * TWOF];
static __device__ __align__(16) float g_colsum[FDIM];
static __device__ unsigned g_mm[4];
static __device__ int g_cnt[NMAX];
static __device__ int g_rowptr[NMAX + 1];
static __device__ int g_cur[NMAX];
static __device__ int g_part[128];
static __device__ __align__(16) uint2 g_edge[EMAX];  // {dst, ew bits} grouped by src

#define MM_BLKS 128
#define HIST_BLKS 256
#define HPREP_BLKS 256
#define WPREP_BLKS 32
#define PREP_BLKS (MM_BLKS + HIST_BLKS + HPREP_BLKS + WPREP_BLKS)
#define RE_BLKS 512

__device__ __forceinline__ unsigned encf(float f) {
    unsigned u = __float_as_uint(f);
    return (u & 0x80000000u) ? ~u : (u | 0x80000000u);
}
__device__ __forceinline__ float decf(unsigned u) {
    return (u & 0x80000000u) ? __uint_as_float(u & 0x7FFFFFFFu) : __uint_as_float(~u);
}
__device__ __forceinline__ void ffma2(unsigned long long& d, unsigned long long a,
                                      unsigned long long b) {
    asm("fma.rn.f32x2 %0, %1, %2, %3;" : "=l"(d) : "l"(a), "l"(b), "l"(d));
}
__device__ __forceinline__ unsigned long long dup2(float x) {
    unsigned long long d;
    unsigned u = __float_as_uint(x);
    asm("mov.b64 %0, {%1, %1};" : "=l"(d) : "r"(u));
    return d;
}
__device__ __forceinline__ void unpack2(unsigned long long v, float& lo, float& hi) {
    unsigned a, b;
    asm("mov.b64 {%0, %1}, %2;" : "=r"(a), "=r"(b) : "l"(v));
    lo = __uint_as_float(a);
    hi = __uint_as_float(b);
}
__device__ __forceinline__ float4 h4_to_f4(uint2 p) {
    float2 lo = __half22float2(*(__half2*)&p.x);
    float2 hi = __half22float2(*(__half2*)&p.y);
    return make_float4(lo.x, lo.y, hi.x, hi.y);
}
// sum two half2-pairs in fp16, convert the SUM once to fp32
__device__ __forceinline__ float4 score_f4u(uint2 p1, unsigned q0, unsigned q1) {
    __half2 s0 = __hadd2(*(__half2*)&p1.x, *(__half2*)&q0);
    __half2 s1 = __hadd2(*(__half2*)&p1.y, *(__half2*)&q1);
    float2 lo = __half22float2(s0);
    float2 hi = __half22float2(s1);
    return make_float4(lo.x, lo.y, hi.x, hi.y);
}
__device__ __forceinline__ float4 h4_to_f4u(unsigned a, unsigned b) {
    float2 lo = __half22float2(*(__half2*)&a);
    float2 hi = __half22float2(*(__half2*)&b);
    return make_float4(lo.x, lo.y, hi.x, hi.y);
}
__device__ __forceinline__ float lrelu_ew(float s, float ew) {
    return (s >= 0.f ? s : NEGSLOPE * s) * ew;
}

// ---------- init ----------
__global__ void k_init(int N) {
    int i = blockIdx.x * 256 + threadIdx.x;
    int4* c4 = (int4*)g_cnt;
    if (i < (N >> 2)) c4[i] = make_int4(0, 0, 0, 0);
    if (i == (N >> 2)) {
        for (int j = N & ~3; j < N; j++) g_cnt[j] = 0;
    }
    if (i < FDIM) g_colsum[i] = 0.0f;
    if (i == 0) {
        g_mm[0] = 0xFFFFFFFFu; g_mm[1] = 0u;
        g_mm[2] = 0xFFFFFFFFu; g_mm[3] = 0u;
    }
}

// ---------- fused prep: minmax | hist | h->fp16 (into g_kv slots) | weight transpose ----------
__global__ void __launch_bounds__(256) k_prep(const float* __restrict__ amount,
                                              const float* __restrict__ count,
                                              const int* __restrict__ adj,
                                              const float* __restrict__ h,
                                              const float* __restrict__ fc_w,
                                              int E, int N) {
    int b = blockIdx.x;
    int tid = threadIdx.x;

    if (b < MM_BLKS) {
        int stride = MM_BLKS * 256;
        float amin = INFINITY, amax = -INFINITY, cmin = INFINITY, cmax = -INFINITY;
        int E4 = E >> 2;
        const float4* a4 = (const float4*)amount;
        const float4* c4 = (const float4*)count;
        for (int i = b * 256 + tid; i < E4; i += stride) {
            float4 a = a4[i], c = c4[i];
            amin = fminf(amin, fminf(fminf(a.x, a.y), fminf(a.z, a.w)));
            amax = fmaxf(amax, fmaxf(fmaxf(a.x, a.y), fmaxf(a.z, a.w)));
            cmin = fminf(cmin, fminf(fminf(c.x, c.y), fminf(c.z, c.w)));
            cmax = fmaxf(cmax, fmaxf(fmaxf(c.x, c.y), fmaxf(c.z, c.w)));
        }
        if (b == 0) {
            for (int i = (E4 << 2) + tid; i < E; i += 256) {
                float a = amount[i], c = count[i];
                amin = fminf(amin, a); amax = fmaxf(amax, a);
                cmin = fminf(cmin, c); cmax = fmaxf(cmax, c);
            }
        }
        #pragma unroll
        for (int off = 16; off; off >>= 1) {
            amin = fminf(amin, __shfl_down_sync(0xFFFFFFFFu, amin, off));
            amax = fmaxf(amax, __shfl_down_sync(0xFFFFFFFFu, amax, off));
            cmin = fminf(cmin, __shfl_down_sync(0xFFFFFFFFu, cmin, off));
            cmax = fmaxf(cmax, __shfl_down_sync(0xFFFFFFFFu, cmax, off));
        }
        __shared__ float red[4][8];
        int w = tid >> 5, l = tid & 31;
        if (l == 0) {
            red[0][w] = amin; red[1][w] = amax;
            red[2][w] = cmin; red[3][w] = cmax;
        }
        __syncthreads();
        if (tid == 0) {
            #pragma unroll
            for (int i = 1; i < 8; i++) {
                red[0][0] = fminf(red[0][0], red[0][i]);
                red[1][0] = fmaxf(red[1][0], red[1][i]);
                red[2][0] = fminf(red[2][0], red[2][i]);
                red[3][0] = fmaxf(red[3][0], red[3][i]);
            }
            atomicMin(&g_mm[0], encf(red[0][0]));
            atomicMax(&g_mm[1], encf(red[1][0]));
            atomicMin(&g_mm[2], encf(red[2][0]));
            atomicMax(&g_mm[3], encf(red[3][0]));
        }
    } else if (b < MM_BLKS + HIST_BLKS) {
        int rb = b - MM_BLKS;
        int stride = HIST_BLKS * 256;
        int E4 = E >> 2;
        const int4* a4 = (const int4*)adj;
        for (int i = rb * 256 + tid; i < E4; i += stride) {
            int4 s = a4[i];
            atomicAdd(&g_cnt[s.x], 1);
            atomicAdd(&g_cnt[s.y], 1);
            atomicAdd(&g_cnt[s.z], 1);
            atomicAdd(&g_cnt[s.w], 1);
        }
        if (rb == 0 && tid < (E & 3)) atomicAdd(&g_cnt[adj[(E & ~3) + tid]], 1);
    } else if (b < MM_BLKS + HIST_BLKS + HPREP_BLKS) {
        // h -> fp16 into g_kv interleaved slots: group l holds h cols 4l..4l+3 at halves l*8+4
        int rb = b - MM_BLKS - HIST_BLKS;
        int stride = HPREP_BLKS * 256;
        int total4 = (N * FDIM) >> 2;   // one float4 = one column group of 4
        for (int i = rb * 256 + tid; i < total4; i += stride) {
            float4 v = ((const float4*)h)[i];
            __half2 a = __floats2half2_rn(v.x, v.y);
            __half2 bb = __floats2half2_rn(v.z, v.w);
            int n = i >> 4, l = i & 15;
            uint2 pk;
            pk.x = *(unsigned*)&a;
            pk.y = *(unsigned*)&bb;
            *(uint2*)(g_kv + (size_t)n * TWOF + l * 8 + 4) = pk;
        }
    } else {
        int idx = (b - MM_BLKS - HIST_BLKS - HPREP_BLKS) * 256 + tid;
        if (idx < FDIM * TWOF) {
            int k = idx >> 7, c = idx & 127;
            g_Wt[idx] = (c < FDIM) ? fc_w[c * TWOF + k]
                                   : fc_w[(c - FDIM) * TWOF + FDIM + k];
        }
    }
}

// ---------- scans ----------
__global__ void __launch_bounds__(256) k_scanA(int N) {
    int base = blockIdx.x * 1024;
    int t = threadIdx.x;
    int s = 0;
    #pragma unroll
    for (int i = t; i < 1024; i += 256) {
        int idx = base + i;
        s += (idx < N) ? g_cnt[idx] : 0;
    }
    __shared__ int red[256];
    red[t] = s;
    __syncthreads();
    #pragma unroll
    for (int off = 128; off; off >>= 1) {
        if (t < off) red[t] += red[t + off];
        __syncthreads();
    }
    if (t == 0) g_part[blockIdx.x] = red[0];
}

__global__ void __launch_bounds__(128) k_scanB(int nchunks, int E, int N) {
    int t = threadIdx.x;
    int v = (t < nchunks) ? g_part[t] : 0;
    __shared__ int sp[128];
    sp[t] = v;
    __syncthreads();
    #pragma unroll
    for (int off = 1; off < 128; off <<= 1) {
        int x = (t >= off) ? sp[t - off] : 0;
        __syncthreads();
        sp[t] += x;
        __syncthreads();
    }
    if (t < nchunks) g_part[t] = sp[t] - v;
    if (t == 0) g_rowptr[N] = E;
}

__global__ void __launch_bounds__(256) k_scanC(int N) {
    int b = blockIdx.x, t = threadIdx.x;
    int base = b * 1024 + t * 4;
    int v[4];
    #pragma unroll
    for (int j = 0; j < 4; j++) v[j] = (base + j < N) ? g_cnt[base + j] : 0;
    int local = v[0] + v[1] + v[2] + v[3];
    __shared__ int sums[256];
    sums[t] = local;
    __syncthreads();
    #pragma unroll
    for (int off = 1; off < 256; off <<= 1) {
        int x = (t >= off) ? sums[t - off] : 0;
        __syncthreads();
        sums[t] += x;
        __syncthreads();
    }
    int excl = sums[t] - local + g_part[b];
    #pragma unroll
    for (int j = 0; j < 4; j++) {
        if (base + j < N) {
            g_rowptr[base + j] = excl;
            g_cur[base + j] = excl;
        }
        excl += v[j];
    }
}

// ---------- fused main: GEMM | edge reorder ----------
#define GN 64
__global__ void __launch_bounds__(256) k_main(const float* __restrict__ h,
                                              const float* __restrict__ fc_b,
                                              const int* __restrict__ adj,
                                              const float* __restrict__ amount,
                                              const float* __restrict__ count,
                                              int E, int N, int gemmBlocks) {
    __shared__ __align__(16) float hs[GN][68];
    int tid = threadIdx.x;

    if ((int)blockIdx.x < gemmBlocks) {
        int n0 = blockIdx.x * GN;
        {
            const float4* h4 = (const float4*)h;
            for (int idx = tid; idx < GN * (FDIM / 4); idx += 256) {
                int n = idx >> 4, kq = idx & 15;
                int gn = n0 + n;
                float4 v = (gn < N) ? h4[(size_t)gn * (FDIM / 4) + kq]
                                    : make_float4(0.f, 0.f, 0.f, 0.f);
                *(float4*)&hs[n][kq * 4] = v;
            }
        }
        __syncthreads();

        int tx = tid & 15, ty = tid >> 4;
        int c0 = tx * 8;
        int nb = ty * 4;

        unsigned long long acc[4][4];
        #pragma unroll
        for (int i = 0; i < 4; i++)
            #pragma unroll
            for (int j = 0; j < 4; j++) acc[i][j] = 0ull;

        #pragma unroll 4
        for (int k = 0; k < FDIM; k++) {
            const ulonglong2* bp = (const ulonglong2*)(g_Wt + k * TWOF + c0);
            ulonglong2 b01 = __ldg(bp);
            ulonglong2 b23 = __ldg(bp + 1);
            #pragma unroll
            for (int i = 0; i < 4; i++) {
                unsigned long long a2 = dup2(hs[nb + i][k]);
                ffma2(acc[i][0], a2, b01.x);
                ffma2(acc[i][1], a2, b01.y);
                ffma2(acc[i][2], a2, b23.x);
                ffma2(acc[i][3], a2, b23.y);
            }
        }

        float bias[8];
        #pragma unroll
        for (int j = 0; j < 8; j++)
            bias[j] = (c0 >= FDIM) ? __ldg(&fc_b[c0 + j - FDIM]) : 0.0f;

        #pragma unroll
        for (int i = 0; i < 4; i++) {
            int gn = n0 + nb + i;
            if (gn >= N) continue;
            float o[8];
            #pragma unroll
            for (int j = 0; j < 4; j++) unpack2(acc[i][j], o[2 * j], o[2 * j + 1]);
            __half2 ha = __floats2half2_rn(o[0] + bias[0], o[1] + bias[1]);
            __half2 hb = __floats2half2_rn(o[2] + bias[2], o[3] + bias[3]);
            __half2 hc = __floats2half2_rn(o[4] + bias[4], o[5] + bias[5]);
            __half2 hd = __floats2half2_rn(o[6] + bias[6], o[7] + bias[7]);
            if (c0 < FDIM) {
                // P1 cols c0..c0+7 -> g_P1
                uint4 pk;
                pk.x = *(unsigned*)&ha; pk.y = *(unsigned*)&hb;
                pk.z = *(unsigned*)&hc; pk.w = *(unsigned*)&hd;
                *(uint4*)(g_P1 + (size_t)gn * FDIM + c0) = pk;
            } else {
                // P2 cols p..p+7 -> interleaved groups l=p/4, l+1 (first 4 halves of each)
                int l = (c0 - FDIM) >> 2;
                uint2 pk0, pk1;
                pk0.x = *(unsigned*)&ha; pk0.y = *(unsigned*)&hb;
                pk1.x = *(unsigned*)&hc; pk1.y = *(unsigned*)&hd;
                *(uint2*)(g_kv + (size_t)gn * TWOF + l * 8) = pk0;
                *(uint2*)(g_kv + (size_t)gn * TWOF + (l + 1) * 8) = pk1;
            }
        }
    } else {
        int rb = blockIdx.x - gemmBlocks;
        float amin = decf(g_mm[0]), amax = decf(g_mm[1]);
        float cmin = decf(g_mm[2]), cmax = decf(g_mm[3]);
        float as = BETA / (amax - amin + 1e-8f);
        float cs = (1.0f - BETA) / (cmax - cmin + 1e-8f);
        int stride = RE_BLKS * 256;
        for (int e = rb * 256 + tid; e < E; e += stride) {
            int s = adj[e];
            int d = adj[E + e];
            float ew = (amount[e] - amin) * as + (count[e] - cmin) * cs;
            int pos = atomicAdd(&g_cur[s], 1);
            g_edge[pos] = make_uint2((unsigned)d, __float_as_uint(ew));
        }
    }
}

// ---------- aggregate: one node per 16-lane group, packed kv gathers ----------
__global__ void __launch_bounds__(256) k_agg(float* __restrict__ out, int N) {
    int lane16 = threadIdx.x & 15;
    int egrp = threadIdx.x >> 4;
    int co = lane16 * 4;
    int kvo = lane16 * 8;   // halves offset of this lane's [P2|h] group

    float4 cacc = make_float4(0.f, 0.f, 0.f, 0.f);

    for (int n = blockIdx.x * 16 + egrp; n < N; n += gridDim.x * 16) {
        int e = g_rowptr[n];
        int end = g_rowptr[n + 1];
        uint2 p1q = *(const uint2*)(g_P1 + (size_t)n * FDIM + co);
        float4 o = make_float4(0.f, 0.f, 0.f, 0.f);

        for (; e + 4 <= end; e += 4) {
            uint2 ed[4];
            uint4 kv[4];
            #pragma unroll
            for (int j = 0; j < 4; j++) ed[j] = __ldg(&g_edge[e + j]);
            #pragma unroll
            for (int j = 0; j < 4; j++)
                kv[j] = *(const uint4*)(g_kv + (size_t)(int)ed[j].x * TWOF + kvo);
            #pragma unroll
            for (int j = 0; j < 4; j++) {
                float ew = __uint_as_float(ed[j].y);
                float4 s = score_f4u(p1q, kv[j].x, kv[j].y);
                float4 hv = h4_to_f4u(kv[j].z, kv[j].w);
                float ex = __expf(lrelu_ew(s.x, ew));
                float ey = __expf(lrelu_ew(s.y, ew));
                float ez = __expf(lrelu_ew(s.z, ew));
                float ew_ = __expf(lrelu_ew(s.w, ew));
                cacc.x += ex; cacc.y += ey; cacc.z += ez; cacc.w += ew_;
                o.x += ex * hv.x; o.y += ey * hv.y; o.z += ez * hv.z; o.w += ew_ * hv.w;
            }
        }
        for (; e < end; e++) {
            uint2 ed0 = __ldg(&g_edge[e]);
            float ew = __uint_as_float(ed0.y);
            uint4 kv = *(const uint4*)(g_kv + (size_t)(int)ed0.x * TWOF + kvo);
            float4 s = score_f4u(p1q, kv.x, kv.y);
            float4 hv = h4_to_f4u(kv.z, kv.w);
            float ex = __expf(lrelu_ew(s.x, ew));
            float ey = __expf(lrelu_ew(s.y, ew));
            float ez = __expf(lrelu_ew(s.z, ew));
            float ew_ = __expf(lrelu_ew(s.w, ew));
            cacc.x += ex; cacc.y += ey; cacc.z += ez; cacc.w += ew_;
            o.x += ex * hv.x; o.y += ey * hv.y; o.z += ez * hv.z; o.w += ew_ * hv.w;
        }
        *(float4*)(out + (size_t)n * FDIM + co) = o;
    }

    __shared__ float scol[FDIM];
    if (threadIdx.x < FDIM) scol[threadIdx.x] = 0.0f;
    __syncthreads();
    atomicAdd(&scol[co + 0], cacc.x);
    atomicAdd(&scol[co + 1], cacc.y);
    atomicAdd(&scol[co + 2], cacc.z);
    atomicAdd(&scol[co + 3], cacc.w);
    __syncthreads();
    if (threadIdx.x < FDIM) atomicAdd(&g_colsum[threadIdx.x], scol[threadIdx.x]);
}

// ---------- normalize ----------
__global__ void __launch_bounds__(256) k_norm(float* __restrict__ out, int total4) {
    int i = blockIdx.x * blockDim.x + threadIdx.x;
    if (i >= total4) return;
    float4 cs4 = *(const float4*)(g_colsum + (i & 15) * 4);
    float4 v = ((float4*)out)[i];
    v.x = __fdividef(v.x, cs4.x);
    v.y = __fdividef(v.y, cs4.y);
    v.z = __fdividef(v.z, cs4.z);
    v.w = __fdividef(v.w, cs4.w);
    ((float4*)out)[i] = v;
}

extern "C" void kernel_launch(void* const* d_in, const int* in_sizes, int n_in,
                              void* d_out, int out_size) {
    const float* h = (const float*)d_in[0];
    const int* adj = (const int*)d_in[1];
    const float* amount = (const float*)d_in[2];
    const float* count = (const float*)d_in[3];
    const float* fc_w = (const float*)d_in[4];
    const float* fc_b = (const float*)d_in[5];
    float* out = (float*)d_out;

    int N = in_sizes[0] / FDIM;
    int E = in_sizes[2];
    int nchunks = (N + 1023) / 1024;
    int gemmBlocks = (N + GN - 1) / GN;

    k_init<<<(N / 4 + 256) / 256, 256>>>(N);
    k_prep<<<PREP_BLKS, 256>>>(amount, count, adj, h, fc_w, E, N);
    k_scanA<<<nchunks, 256>>>(N);
    k_scanB<<<1, 128>>>(nchunks, E, N);
    k_scanC<<<nchunks, 256>>>(N);
    k_main<<<gemmBlocks + RE_BLKS, 256>>>(h, fc_b, adj, amount, count, E, N, gemmBlocks);
    k_agg<<<(N + 15) / 16, 256>>>(out, N);
    int total4 = out_size / 4;
    k_norm<<<(total4 + 255) / 256, 256>>>(out, total4);
}

// round 15
// speedup vs baseline: 1.0759x; 1.0150x over previous
#include <cuda_runtime.h>
#include <cuda_fp16.h>
#include <cstdint>

#define FDIM 64
#define TWOF 128
#define NMAX 100000
#define EMAX 2000000
#define BETA 0.5f
#define NEGSLOPE 0.01f

static __device__ __align__(16) __half g_P1[(size_t)NMAX * FDIM];   // P1 (cols 0..63), fp16
// interleaved per node: 16 groups of [P2(4 cols) | h(4 cols)] halves
static __device__ __align__(16) __half g_kv[(size_t)NMAX * TWOF];
static __device__ __align__(16) float g_Wt[FDIM * TWOF];
static __device__ __align__(16) float g_colsum[FDIM];
static __device__ unsigned g_mm[4];
static __device__ int g_cnt[NMAX];
static __device__ int g_rowptr[NMAX + 1];
static __device__ int g_cur[NMAX];
static __device__ int g_part[128];
static __device__ __align__(16) uint2 g_edge[EMAX];  // {dst, ew bits} grouped by src

#define MM_BLKS 128
#define HIST_BLKS 256
#define HPREP_BLKS 256
#define WPREP_BLKS 32
#define PREP_BLKS (MM_BLKS + HIST_BLKS + HPREP_BLKS + WPREP_BLKS)
#define RE_BLKS 512

__device__ __forceinline__ unsigned encf(float f) {
    unsigned u = __float_as_uint(f);
    return (u & 0x80000000u) ? ~u : (u | 0x80000000u);
}
__device__ __forceinline__ float decf(unsigned u) {
    return (u & 0x80000000u) ? __uint_as_float(u & 0x7FFFFFFFu) : __uint_as_float(~u);
}
__device__ __forceinline__ void ffma2(unsigned long long& d, unsigned long long a,
                                      unsigned long long b) {
    asm("fma.rn.f32x2 %0, %1, %2, %3;" : "=l"(d) : "l"(a), "l"(b), "l"(d));
}
__device__ __forceinline__ unsigned long long dup2(float x) {
    unsigned long long d;
    unsigned u = __float_as_uint(x);
    asm("mov.b64 %0, {%1, %1};" : "=l"(d) : "r"(u));
    return d;
}
__device__ __forceinline__ void unpack2(unsigned long long v, float& lo, float& hi) {
    unsigned a, b;
    asm("mov.b64 {%0, %1}, %2;" : "=r"(a), "=r"(b) : "l"(v));
    lo = __uint_as_float(a);
    hi = __uint_as_float(b);
}
// sum two half2-pairs in fp16, convert the SUM once to fp32
__device__ __forceinline__ float4 score_f4u(uint2 p1, unsigned q0, unsigned q1) {
    __half2 s0 = __hadd2(*(__half2*)&p1.x, *(__half2*)&q0);
    __half2 s1 = __hadd2(*(__half2*)&p1.y, *(__half2*)&q1);
    float2 lo = __half22float2(s0);
    float2 hi = __half22float2(s1);
    return make_float4(lo.x, lo.y, hi.x, hi.y);
}
__device__ __forceinline__ float4 h4_to_f4u(unsigned a, unsigned b) {
    float2 lo = __half22float2(*(__half2*)&a);
    float2 hi = __half22float2(*(__half2*)&b);
    return make_float4(lo.x, lo.y, hi.x, hi.y);
}
__device__ __forceinline__ float lrelu_ew(float s, float ew) {
    return (s >= 0.f ? s : NEGSLOPE * s) * ew;
}

// per-edge contribution (4 cols per lane), fp32 math — bit-identical to R14
__device__ __forceinline__ void edge_contrib(uint2 p1q, uint4 kv, float ew,
                                             float4& cacc, float4& o) {
    float4 s = score_f4u(p1q, kv.x, kv.y);
    float4 hv = h4_to_f4u(kv.z, kv.w);
    float ex = __expf(lrelu_ew(s.x, ew));
    float ey = __expf(lrelu_ew(s.y, ew));
    float ez = __expf(lrelu_ew(s.z, ew));
    float ew_ = __expf(lrelu_ew(s.w, ew));
    cacc.x += ex; cacc.y += ey; cacc.z += ez; cacc.w += ew_;
    o.x += ex * hv.x; o.y += ey * hv.y; o.z += ez * hv.z; o.w += ew_ * hv.w;
}

// ---------- init ----------
__global__ void k_init(int N) {
    int i = blockIdx.x * 256 + threadIdx.x;
    int4* c4 = (int4*)g_cnt;
    if (i < (N >> 2)) c4[i] = make_int4(0, 0, 0, 0);
    if (i == (N >> 2)) {
        for (int j = N & ~3; j < N; j++) g_cnt[j] = 0;
    }
    if (i < FDIM) g_colsum[i] = 0.0f;
    if (i == 0) {
        g_mm[0] = 0xFFFFFFFFu; g_mm[1] = 0u;
        g_mm[2] = 0xFFFFFFFFu; g_mm[3] = 0u;
    }
}

// ---------- fused prep: minmax | hist | h->fp16 (into g_kv slots) | weight transpose ----------
__global__ void __launch_bounds__(256) k_prep(const float* __restrict__ amount,
                                              const float* __restrict__ count,
                                              const int* __restrict__ adj,
                                              const float* __restrict__ h,
                                              const float* __restrict__ fc_w,
                                              int E, int N) {
    int b = blockIdx.x;
    int tid = threadIdx.x;

    if (b < MM_BLKS) {
        int stride = MM_BLKS * 256;
        float amin = INFINITY, amax = -INFINITY, cmin = INFINITY, cmax = -INFINITY;
        int E4 = E >> 2;
        const float4* a4 = (const float4*)amount;
        const float4* c4 = (const float4*)count;
        for (int i = b * 256 + tid; i < E4; i += stride) {
            float4 a = a4[i], c = c4[i];
            amin = fminf(amin, fminf(fminf(a.x, a.y), fminf(a.z, a.w)));
            amax = fmaxf(amax, fmaxf(fmaxf(a.x, a.y), fmaxf(a.z, a.w)));
            cmin = fminf(cmin, fminf(fminf(c.x, c.y), fminf(c.z, c.w)));
            cmax = fmaxf(cmax, fmaxf(fmaxf(c.x, c.y), fmaxf(c.z, c.w)));
        }
        if (b == 0) {
            for (int i = (E4 << 2) + tid; i < E; i += 256) {
                float a = amount[i], c = count[i];
                amin = fminf(amin, a); amax = fmaxf(amax, a);
                cmin = fminf(cmin, c); cmax = fmaxf(cmax, c);
            }
        }
        #pragma unroll
        for (int off = 16; off; off >>= 1) {
            amin = fminf(amin, __shfl_down_sync(0xFFFFFFFFu, amin, off));
            amax = fmaxf(amax, __shfl_down_sync(0xFFFFFFFFu, amax, off));
            cmin = fminf(cmin, __shfl_down_sync(0xFFFFFFFFu, cmin, off));
            cmax = fmaxf(cmax, __shfl_down_sync(0xFFFFFFFFu, cmax, off));
        }
        __shared__ float red[4][8];
        int w = tid >> 5, l = tid & 31;
        if (l == 0) {
            red[0][w] = amin; red[1][w] = amax;
            red[2][w] = cmin; red[3][w] = cmax;
        }
        __syncthreads();
        if (tid == 0) {
            #pragma unroll
            for (int i = 1; i < 8; i++) {
                red[0][0] = fminf(red[0][0], red[0][i]);
                red[1][0] = fmaxf(red[1][0], red[1][i]);
                red[2][0] = fminf(red[2][0], red[2][i]);
                red[3][0] = fmaxf(red[3][0], red[3][i]);
            }
            atomicMin(&g_mm[0], encf(red[0][0]));
            atomicMax(&g_mm[1], encf(red[1][0]));
            atomicMin(&g_mm[2], encf(red[2][0]));
            atomicMax(&g_mm[3], encf(red[3][0]));
        }
    } else if (b < MM_BLKS + HIST_BLKS) {
        int rb = b - MM_BLKS;
        int stride = HIST_BLKS * 256;
        int E4 = E >> 2;
        const int4* a4 = (const int4*)adj;
        for (int i = rb * 256 + tid; i < E4; i += stride) {
            int4 s = a4[i];
            atomicAdd(&g_cnt[s.x], 1);
            atomicAdd(&g_cnt[s.y], 1);
            atomicAdd(&g_cnt[s.z], 1);
            atomicAdd(&g_cnt[s.w], 1);
        }
        if (rb == 0 && tid < (E & 3)) atomicAdd(&g_cnt[adj[(E & ~3) + tid]], 1);
    } else if (b < MM_BLKS + HIST_BLKS + HPREP_BLKS) {
        // h -> fp16 into g_kv interleaved slots: group l holds h cols 4l..4l+3 at halves l*8+4
        int rb = b - MM_BLKS - HIST_BLKS;
        int stride = HPREP_BLKS * 256;
        int total4 = (N * FDIM) >> 2;
        for (int i = rb * 256 + tid; i < total4; i += stride) {
            float4 v = ((const float4*)h)[i];
            __half2 a = __floats2half2_rn(v.x, v.y);
            __half2 bb = __floats2half2_rn(v.z, v.w);
            int n = i >> 4, l = i & 15;
            uint2 pk;
            pk.x = *(unsigned*)&a;
            pk.y = *(unsigned*)&bb;
            *(uint2*)(g_kv + (size_t)n * TWOF + l * 8 + 4) = pk;
        }
    } else {
        int idx = (b - MM_BLKS - HIST_BLKS - HPREP_BLKS) * 256 + tid;
        if (idx < FDIM * TWOF) {
            int k = idx >> 7, c = idx & 127;
            g_Wt[idx] = (c < FDIM) ? fc_w[c * TWOF + k]
                                   : fc_w[(c - FDIM) * TWOF + FDIM + k];
        }
    }
}

// ---------- scans ----------
__global__ void __launch_bounds__(256) k_scanA(int N) {
    int base = blockIdx.x * 1024;
    int t = threadIdx.x;
    int s = 0;
    #pragma unroll
    for (int i = t; i < 1024; i += 256) {
        int idx = base + i;
        s += (idx < N) ? g_cnt[idx] : 0;
    }
    __shared__ int red[256];
    red[t] = s;
    __syncthreads();
    #pragma unroll
    for (int off = 128; off; off >>= 1) {
        if (t < off) red[t] += red[t + off];
        __syncthreads();
    }
    if (t == 0) g_part[blockIdx.x] = red[0];
}

__global__ void __launch_bounds__(128) k_scanB(int nchunks, int E, int N) {
    int t = threadIdx.x;
    int v = (t < nchunks) ? g_part[t] : 0;
    __shared__ int sp[128];
    sp[t] = v;
    __syncthreads();
    #pragma unroll
    for (int off = 1; off < 128; off <<= 1) {
        int x = (t >= off) ? sp[t - off] : 0;
        __syncthreads();
        sp[t] += x;
        __syncthreads();
    }
    if (t < nchunks) g_part[t] = sp[t] - v;
    if (t == 0) g_rowptr[N] = E;
}

__global__ void __launch_bounds__(256) k_scanC(int N) {
    int b = blockIdx.x, t = threadIdx.x;
    int base = b * 1024 + t * 4;
    int v[4];
    #pragma unroll
    for (int j = 0; j < 4; j++) v[j] = (base + j < N) ? g_cnt[base + j] : 0;
    int local = v[0] + v[1] + v[2] + v[3];
    __shared__ int sums[256];
    sums[t] = local;
    __syncthreads();
    #pragma unroll
    for (int off = 1; off < 256; off <<= 1) {
        int x = (t >= off) ? sums[t - off] : 0;
        __syncthreads();
        sums[t] += x;
        __syncthreads();
    }
    int excl = sums[t] - local + g_part[b];
    #pragma unroll
    for (int j = 0; j < 4; j++) {
        if (base + j < N) {
            g_rowptr[base + j] = excl;
            g_cur[base + j] = excl;
        }
        excl += v[j];
    }
}

// ---------- fused main: GEMM | edge reorder ----------
#define GN 64
__global__ void __launch_bounds__(256) k_main(const float* __restrict__ h,
                                              const float* __restrict__ fc_b,
                                              const int* __restrict__ adj,
                                              const float* __restrict__ amount,
                                              const float* __restrict__ count,
                                              int E, int N, int gemmBlocks) {
    __shared__ __align__(16) float hs[GN][68];
    int tid = threadIdx.x;

    if ((int)blockIdx.x < gemmBlocks) {
        int n0 = blockIdx.x * GN;
        {
            const float4* h4 = (const float4*)h;
            for (int idx = tid; idx < GN * (FDIM / 4); idx += 256) {
                int n = idx >> 4, kq = idx & 15;
                int gn = n0 + n;
                float4 v = (gn < N) ? h4[(size_t)gn * (FDIM / 4) + kq]
                                    : make_float4(0.f, 0.f, 0.f, 0.f);
                *(float4*)&hs[n][kq * 4] = v;
            }
        }
        __syncthreads();

        int tx = tid & 15, ty = tid >> 4;
        int c0 = tx * 8;
        int nb = ty * 4;

        unsigned long long acc[4][4];
        #pragma unroll
        for (int i = 0; i < 4; i++)
            #pragma unroll
            for (int j = 0; j < 4; j++) acc[i][j] = 0ull;

        #pragma unroll 4
        for (int k = 0; k < FDIM; k++) {
            const ulonglong2* bp = (const ulonglong2*)(g_Wt + k * TWOF + c0);
            ulonglong2 b01 = __ldg(bp);
            ulonglong2 b23 = __ldg(bp + 1);
            #pragma unroll
            for (int i = 0; i < 4; i++) {
                unsigned long long a2 = dup2(hs[nb + i][k]);
                ffma2(acc[i][0], a2, b01.x);
                ffma2(acc[i][1], a2, b01.y);
                ffma2(acc[i][2], a2, b23.x);
                ffma2(acc[i][3], a2, b23.y);
            }
        }

        float bias[8];
        #pragma unroll
        for (int j = 0; j < 8; j++)
            bias[j] = (c0 >= FDIM) ? __ldg(&fc_b[c0 + j - FDIM]) : 0.0f;

        #pragma unroll
        for (int i = 0; i < 4; i++) {
            int gn = n0 + nb + i;
            if (gn >= N) continue;
            float o[8];
            #pragma unroll
            for (int j = 0; j < 4; j++) unpack2(acc[i][j], o[2 * j], o[2 * j + 1]);
            __half2 ha = __floats2half2_rn(o[0] + bias[0], o[1] + bias[1]);
            __half2 hb = __floats2half2_rn(o[2] + bias[2], o[3] + bias[3]);
            __half2 hc = __floats2half2_rn(o[4] + bias[4], o[5] + bias[5]);
            __half2 hd = __floats2half2_rn(o[6] + bias[6], o[7] + bias[7]);
            if (c0 < FDIM) {
                uint4 pk;
                pk.x = *(unsigned*)&ha; pk.y = *(unsigned*)&hb;
                pk.z = *(unsigned*)&hc; pk.w = *(unsigned*)&hd;
                *(uint4*)(g_P1 + (size_t)gn * FDIM + c0) = pk;
            } else {
                int l = (c0 - FDIM) >> 2;
                uint2 pk0, pk1;
                pk0.x = *(unsigned*)&ha; pk0.y = *(unsigned*)&hb;
                pk1.x = *(unsigned*)&hc; pk1.y = *(unsigned*)&hd;
                *(uint2*)(g_kv + (size_t)gn * TWOF + l * 8) = pk0;
                *(uint2*)(g_kv + (size_t)gn * TWOF + (l + 1) * 8) = pk1;
            }
        }
    } else {
        int rb = blockIdx.x - gemmBlocks;
        float amin = decf(g_mm[0]), amax = decf(g_mm[1]);
        float cmin = decf(g_mm[2]), cmax = decf(g_mm[3]);
        float as = BETA / (amax - amin + 1e-8f);
        float cs = (1.0f - BETA) / (cmax - cmin + 1e-8f);
        int stride = RE_BLKS * 256;
        for (int e = rb * 256 + tid; e < E; e += stride) {
            int s = adj[e];
            int d = adj[E + e];
            float ew = (amount[e] - amin) * as + (count[e] - cmin) * cs;
            int pos = atomicAdd(&g_cur[s], 1);
            g_edge[pos] = make_uint2((unsigned)d, __float_as_uint(ew));
        }
    }
}

// ---------- aggregate: one node per 16-lane group, software-pipelined edge loop ----------
__global__ void __launch_bounds__(256) k_agg(float* __restrict__ out, int N) {
    int lane16 = threadIdx.x & 15;
    int egrp = threadIdx.x >> 4;
    int co = lane16 * 4;
    int kvo = lane16 * 8;

    float4 cacc = make_float4(0.f, 0.f, 0.f, 0.f);

    for (int n = blockIdx.x * 16 + egrp; n < N; n += gridDim.x * 16) {
        int e = g_rowptr[n];
        int end = g_rowptr[n + 1];
        uint2 p1q = *(const uint2*)(g_P1 + (size_t)n * FDIM + co);
        float4 o = make_float4(0.f, 0.f, 0.f, 0.f);

        uint2 edc[4];
        if (e + 4 <= end) {
            #pragma unroll
            for (int j = 0; j < 4; j++) edc[j] = __ldg(&g_edge[e + j]);
        }
        // pipelined main loop: prefetch next quad before consuming current
        for (; e + 8 <= end; e += 4) {
            uint2 edn[4];
            #pragma unroll
            for (int j = 0; j < 4; j++) edn[j] = __ldg(&g_edge[e + 4 + j]);
            uint4 kv[4];
            #pragma unroll
            for (int j = 0; j < 4; j++)
                kv[j] = *(const uint4*)(g_kv + (size_t)(int)edc[j].x * TWOF + kvo);
            #pragma unroll
            for (int j = 0; j < 4; j++)
                edge_contrib(p1q, kv[j], __uint_as_float(edc[j].y), cacc, o);
            #pragma unroll
            for (int j = 0; j < 4; j++) edc[j] = edn[j];
        }
        // drain the last full quad (already loaded in edc)
        if (e + 4 <= end) {
            uint4 kv[4];
            #pragma unroll
            for (int j = 0; j < 4; j++)
                kv[j] = *(const uint4*)(g_kv + (size_t)(int)edc[j].x * TWOF + kvo);
            #pragma unroll
            for (int j = 0; j < 4; j++)
                edge_contrib(p1q, kv[j], __uint_as_float(edc[j].y), cacc, o);
            e += 4;
        }
        // remainder (< 4 edges)
        for (; e < end; e++) {
            uint2 ed0 = __ldg(&g_edge[e]);
            uint4 kv = *(const uint4*)(g_kv + (size_t)(int)ed0.x * TWOF + kvo);
            edge_contrib(p1q, kv, __uint_as_float(ed0.y), cacc, o);
        }
        *(float4*)(out + (size_t)n * FDIM + co) = o;
    }

    __shared__ float scol[FDIM];
    if (threadIdx.x < FDIM) scol[threadIdx.x] = 0.0f;
    __syncthreads();
    atomicAdd(&scol[co + 0], cacc.x);
    atomicAdd(&scol[co + 1], cacc.y);
    atomicAdd(&scol[co + 2], cacc.z);
    atomicAdd(&scol[co + 3], cacc.w);
    __syncthreads();
    if (threadIdx.x < FDIM) atomicAdd(&g_colsum[threadIdx.x], scol[threadIdx.x]);
}

// ---------- normalize ----------
__global__ void __launch_bounds__(256) k_norm(float* __restrict__ out, int total4) {
    int i = blockIdx.x * blockDim.x + threadIdx.x;
    if (i >= total4) return;
    float4 cs4 = *(const float4*)(g_colsum + (i & 15) * 4);
    float4 v = ((float4*)out)[i];
    v.x = __fdividef(v.x, cs4.x);
    v.y = __fdividef(v.y, cs4.y);
    v.z = __fdividef(v.z, cs4.z);
    v.w = __fdividef(v.w, cs4.w);
    ((float4*)out)[i] = v;
}

extern "C" void kernel_launch(void* const* d_in, const int* in_sizes, int n_in,
                              void* d_out, int out_size) {
    const float* h = (const float*)d_in[0];
    const int* adj = (const int*)d_in[1];
    const float* amount = (const float*)d_in[2];
    const float* count = (const float*)d_in[3];
    const float* fc_w = (const float*)d_in[4];
    const float* fc_b = (const float*)d_in[5];
    float* out = (float*)d_out;

    int N = in_sizes[0] / FDIM;
    int E = in_sizes[2];
    int nchunks = (N + 1023) / 1024;
    int gemmBlocks = (N + GN - 1) / GN;

    k_init<<<(N / 4 + 256) / 256, 256>>>(N);
    k_prep<<<PREP_BLKS, 256>>>(amount, count, adj, h, fc_w, E, N);
    k_scanA<<<nchunks, 256>>>(N);
    k_scanB<<<1, 128>>>(nchunks, E, N);
    k_scanC<<<nchunks, 256>>>(N);
    k_main<<<gemmBlocks + RE_BLKS, 256>>>(h, fc_b, adj, amount, count, E, N, gemmBlocks);
    k_agg<<<(N + 15) / 16, 256>>>(out, N);
    int total4 = out_size / 4;
    k_norm<<<(total4 + 255) / 256, 256>>>(out, total4);
}